// round 15
// baseline (speedup 1.0000x reference)
#include <cuda_runtime.h>
#include <stdint.h>

// ---------------- problem constants (B=16, H=W=64, A=9, K=50) ----------------
#define A_LOC 9
#define HW    64
#define LOCS  (HW*HW)          // 4096
#define NANCH (LOCS*A_LOC)     // 36864
#define MAXB  16
#define MAXK  64
#define SLOTS 6
#define TCAP  512

// shape-major storage index for anchor (a, loc):  a*LOCS + loc
// original (reference) anchor index:              loc*A_LOC + a

// ---------------- device scratch (no allocations allowed) --------------------
__device__ float              g_maxovr[MAXB*NANCH];     // shape-major; -1 = outside
__device__ unsigned char      g_arg   [MAXB*NANCH];     // shape-major
__device__ signed char        g_lbl   [MAXB*NANCH];     // shape-major; -2 out,-1 dc,0 bg,1 fg
__device__ unsigned char      g_ccnt  [MAXB*NANCH];     // candidate count (sat 255)
__device__ unsigned long long g_cand  [(size_t)MAXB*NANCH*SLOTS]; // (ovr_bits<<32)|k
__device__ int                g_gtmax [MAXB*MAXK];      // float bits; zeroed by k_out
__device__ float              g_uw    [MAXB];
__device__ int                g_cnt   [MAXB*2];         // fg,bg counts; zeroed by k_out
__device__ int                g_done  [MAXB];           // per-batch block counters (self-reset)
__device__ unsigned long long g_fg    [MAXB*NANCH];     // (prio<<32)|orig_n
__device__ unsigned long long g_bg    [MAXB*NANCH];

// 9 base anchors (exact integers), order: ratio {0.5,1,2} x scale {8,16,32}
__constant__ float c_base[36] = {
  -84.f, -40.f,  99.f,  55.f,
 -176.f, -88.f, 191.f, 103.f,
 -360.f,-184.f, 375.f, 199.f,
  -56.f, -56.f,  71.f,  71.f,
 -120.f,-120.f, 135.f, 135.f,
 -248.f,-248.f, 263.f, 263.f,
  -36.f, -80.f,  51.f,  95.f,
  -80.f,-168.f,  95.f, 183.f,
 -168.f,-344.f, 183.f, 359.f
};

// ---------------- threefry2x32 (20 rounds), matches jax threefry2x32_p -------
__device__ __forceinline__ void tf_round(unsigned &x0, unsigned &x1, int r){
  x0 += x1; x1 = (x1 << r) | (x1 >> (32 - r)); x1 ^= x0;
}
__device__ __forceinline__ uint2 threefry(unsigned k0, unsigned k1,
                                          unsigned x0, unsigned x1){
  unsigned k2 = k0 ^ k1 ^ 0x1BD11BDAu;
  x0 += k0; x1 += k1;
  tf_round(x0,x1,13); tf_round(x0,x1,15); tf_round(x0,x1,26); tf_round(x0,x1,6);
  x0 += k1; x1 += k2 + 1u;
  tf_round(x0,x1,17); tf_round(x0,x1,29); tf_round(x0,x1,16); tf_round(x0,x1,24);
  x0 += k2; x1 += k0 + 2u;
  tf_round(x0,x1,13); tf_round(x0,x1,15); tf_round(x0,x1,26); tf_round(x0,x1,6);
  x0 += k0; x1 += k1 + 3u;
  tf_round(x0,x1,17); tf_round(x0,x1,29); tf_round(x0,x1,16); tf_round(x0,x1,24);
  x0 += k1; x1 += k2 + 4u;
  tf_round(x0,x1,13); tf_round(x0,x1,15); tf_round(x0,x1,26); tf_round(x0,x1,6);
  x0 += k2; x1 += k0 + 5u;
  return make_uint2(x0, x1);
}
__device__ __forceinline__ unsigned uniform_m23(unsigned k0, unsigned k1, unsigned idx){
  uint2 r = threefry(k0, k1, 0u, idx);
  return (r.x ^ r.y) >> 9;   // 23-bit mantissa bits; monotone in the uniform value
}

// exact IoU with reference rounding (strict rn ops, no fma contraction)
__device__ __forceinline__ float iou_exact(float ax1,float ay1,float ax2,float ay2,
                                           float aarea,
                                           float g0,float g1,float g2,float g3,float ga){
  float ix = fmaxf(0.f, __fadd_rn(__fsub_rn(fminf(ax2,g2), fmaxf(ax1,g0)),1.f));
  float iy = fmaxf(0.f, __fadd_rn(__fsub_rn(fminf(ay2,g3), fmaxf(ay1,g1)),1.f));
  float inter = __fmul_rn(ix, iy);
  float uni   = __fsub_rn(__fadd_rn(aarea, ga), inter);
  return __fdiv_rn(inter, uni);
}

// ---------------- kernel 1: IoU via intersection bitmasks --------------------
// Requires g_gtmax == 0 on entry (restored by k_out at end of previous launch).
__global__ void k_iou(const float* __restrict__ gt, const float* __restrict__ iminfo, int K){
  int b = blockIdx.y;
  __shared__ float4 s_rej[MAXK];               // (g0-1.001, g2+1.001, g1-1.001, g3+1.001)
  __shared__ float4 s_box[MAXK];               // exact gt coords
  __shared__ float  s_area[MAXK];
  __shared__ int    s_gm[MAXK];
  __shared__ unsigned long long s_xmask[64];
  __shared__ unsigned long long s_ymask[4];
  int t = threadIdx.x;
  int idx0 = blockIdx.x*blockDim.x;           // shape-major base for this block
  int a    = idx0 >> 12;
  int y0b  = (idx0 & (LOCS-1)) >> 6;          // first y row of the 4-row band
  float imh = iminfo[0], imw = iminfo[1];
  float bx1a = c_base[a*4+0], by1a = c_base[a*4+1];
  float bx2a = c_base[a*4+2], by2a = c_base[a*4+3];
  if (t < MAXK) s_gm[t] = 0;
  if (t < K){
    float g0 = gt[(b*K+t)*5+0], g1 = gt[(b*K+t)*5+1];
    float g2 = gt[(b*K+t)*5+2], g3 = gt[(b*K+t)*5+3];
    s_box[t] = make_float4(g0, g1, g2, g3);
    s_rej[t] = make_float4(g0 - 1.001f, g2 + 1.001f, g1 - 1.001f, g3 + 1.001f);
    float ga = __fmul_rn(__fadd_rn(__fsub_rn(g2,g0),1.f),
                         __fadd_rn(__fsub_rn(g3,g1),1.f));
    s_area[t] = ga;
    // ---- prime s_gm[t] with one heuristic probe anchor (sound lower bound) ----
    float gw = g2-g0+1.f, gh = g3-g1+1.f;
    int r  = (gw > 1.42f*gh) ? 0 : ((gh > 1.42f*gw) ? 2 : 1);
    float m = fmaxf(gw, gh);
    int sc = (m < 181.f) ? 0 : ((m < 362.f) ? 1 : 2);
    int pa = r*3 + sc;
    float bx1 = c_base[pa*4+0], by1 = c_base[pa*4+1];
    float bx2 = c_base[pa*4+2], by2 = c_base[pa*4+3];
    int xlo = (int)ceilf(-bx1*0.0625f);          if (xlo < 0)  xlo = 0;
    int xhi = (int)ceilf((imw-bx2)*0.0625f) - 1; if (xhi > 63) xhi = 63;
    int ylo = (int)ceilf(-by1*0.0625f);          if (ylo < 0)  ylo = 0;
    int yhi = (int)ceilf((imh-by2)*0.0625f) - 1; if (yhi > 63) yhi = 63;
    if (xlo <= xhi && ylo <= yhi){
      float gcx = 0.5f*(g0+g2), gcy = 0.5f*(g1+g3);
      int px = __float2int_rn((gcx - 7.5f)*0.0625f);
      int py = __float2int_rn((gcy - 7.5f)*0.0625f);
      px = px < xlo ? xlo : (px > xhi ? xhi : px);
      py = py < ylo ? ylo : (py > yhi ? yhi : py);
      float ax1 = bx1 + 16.f*(float)px, ay1 = by1 + 16.f*(float)py;
      float ax2 = bx2 + 16.f*(float)px, ay2 = by2 + 16.f*(float)py;
      if (ax1 >= 0.f && ay1 >= 0.f && ax2 < imw && ay2 < imh){   // exact inside
        float aw = __fadd_rn(__fsub_rn(ax2,ax1),1.f);
        float ah = __fadd_rn(__fsub_rn(ay2,ay1),1.f);
        float aarea = __fmul_rn(aw, ah);
        float o = iou_exact(ax1,ay1,ax2,ay2,aarea, g0,g1,g2,g3,ga);
        if (o > 0.f) s_gm[t] = (int)__float_as_int(o);
      }
    }
  }
  __syncthreads();
  // ---- build column/row intersection bitmasks (conservative superset) ----
  if (t < 64){
    float ax1 = bx1a + 16.f*(float)t;
    float ax2 = bx2a + 16.f*(float)t;
    unsigned long long m = 0ull;
    for (int k = 0; k < K; k++){
      float4 rj = s_rej[k];
      if (ax2 > rj.x && ax1 < rj.y) m |= 1ull << k;
    }
    s_xmask[t] = m;
  } else if (t < 68){
    int row = t - 64;
    float ay1 = by1a + 16.f*(float)(y0b + row);
    float ay2 = by2a + 16.f*(float)(y0b + row);
    unsigned long long m = 0ull;
    for (int k = 0; k < K; k++){
      float4 rj = s_rej[k];
      if (ay2 > rj.z && ay1 < rj.w) m |= 1ull << k;
    }
    s_ymask[row] = m;
  }
  __syncthreads();

  int idx2 = idx0 + t;
  int loc = idx2 & (LOCS-1);
  int x = loc & (HW-1), y = loc >> 6;
  float ax1 = bx1a + 16.f*(float)x;
  float ay1 = by1a + 16.f*(float)y;
  float ax2 = bx2a + 16.f*(float)x;
  float ay2 = by2a + 16.f*(float)y;
  bool inside = (ax1 >= 0.f) && (ay1 >= 0.f) && (ax2 < imw) && (ay2 < imh);
  int sidx = b*NANCH + idx2;
  volatile int* vgm = s_gm;

  if (inside){
    float aw = __fadd_rn(__fsub_rn(ax2,ax1),1.f);
    float ah = __fadd_rn(__fsub_rn(ay2,ay1),1.f);
    float aarea = __fmul_rn(aw, ah);
    float mo = 0.f; int ma = 0, ccnt = 0;
    unsigned long long m = s_xmask[x] & s_ymask[y - y0b];
    while (m){
      int k = __ffsll((long long)m) - 1;        // ascending k => argmax = first max
      m &= m - 1ull;
      float4 gb = s_box[k];
      float ix = __fadd_rn(__fsub_rn(fminf(ax2,gb.z), fmaxf(ax1,gb.x)),1.f);
      float iy = __fadd_rn(__fsub_rn(fminf(ay2,gb.w), fmaxf(ay1,gb.y)),1.f);
      if (ix > 0.f && iy > 0.f){                // exact decision, unchanged
        float inter = __fmul_rn(ix, iy);
        float uni   = __fsub_rn(__fadd_rn(aarea, s_area[k]), inter);
        float ovr   = __fdiv_rn(inter, uni);
        if (ovr > mo){ mo = ovr; ma = k; }
        int bits = (int)__float_as_int(ovr);    // ovr > 0 => positive int order
        int cur = vgm[k];                       // broadcast LDS, conflict-free
        if (bits >= cur){                       // can still tie the final max
          atomicMax(&s_gm[k], bits);
          if (ccnt < SLOTS)
            g_cand[(size_t)sidx*SLOTS + ccnt] =
              ((unsigned long long)(unsigned)bits << 32) | (unsigned)k;
          ccnt++;
        }
      }
    }
    g_maxovr[sidx] = mo;
    g_arg   [sidx] = (unsigned char)ma;
    g_ccnt  [sidx] = (unsigned char)(ccnt > 255 ? 255 : ccnt);
  } else {
    g_maxovr[sidx] = -1.f;
  }
  __syncthreads();
  if (t < K && s_gm[t]) atomicMax(&g_gtmax[b*MAXK+t], s_gm[t]);
}

// ---------------- selection helper (256 threads, 2048 bins, 12KB smem) -------
__device__ __forceinline__ int sm_idx_of_n(int n){  // original n -> shape-major idx
  int a = n % A_LOC, loc = n / A_LOC;
  return a*LOCS + loc;
}

// Keep top-`limit` by (prio desc, index asc); mark the rest -1 in g_lbl.
__device__ void do_select_256(const unsigned long long* __restrict__ list,
                              int b, int cnt, int limit,
                              int* hist, int* s_w8, unsigned long long* s_list, int* s_s){
  const int tid = threadIdx.x;                  // 0..255
  if (cnt <= limit) return;                     // uniform condition

  // histogram: 2048 bins on prio[22:12]
  for (int i = tid; i < 2048; i += 256) hist[i] = 0;
  __syncthreads();
  for (int i = tid; i < cnt; i += 256)
    atomicAdd(&hist[(unsigned)(list[i] >> 32) >> 12], 1);
  __syncthreads();
  int v = 0;
#pragma unroll
  for (int q = 0; q < 8; q++) v += hist[8*tid + q];
  // suffix scan over 256 threads (8 warps)
  int lane = tid & 31, wrp = tid >> 5;
  int s = v;
#pragma unroll
  for (int off = 1; off < 32; off <<= 1){
    int o = __shfl_down_sync(0xffffffffu, s, off);
    if (lane + off < 32) s += o;
  }
  if (lane == 0) s_w8[wrp] = s;
  __syncthreads();
  if (tid == 0){
    int acc = 0;
    for (int j = 7; j >= 0; j--){ int tmp = s_w8[j]; s_w8[j] = acc; acc += tmp; }
  }
  __syncthreads();
  int S = s + s_w8[wrp];                        // suffix incl own value
  if (S >= limit && S - v < limit){ s_s[0] = tid; s_s[1] = S - v; }
  __syncthreads();
  if (tid == 0){
    int g = s_s[0], acc = s_s[1];
    for (int q = 8*g+7; q >= 8*g; q--){
      acc += hist[q];
      if (acc >= limit){ s_s[2] = q; s_s[3] = limit - (acc - hist[q]); break; }
    }
    s_s[4] = 0;
  }
  __syncthreads();
  int bin = s_s[2], rem = s_s[3];

  // single disable/collect pass: bins below -> disable; boundary bin -> collect
  for (int i = tid; i < cnt; i += 256){
    unsigned long long e = list[i];
    int bb = (int)((unsigned)(e >> 32) >> 12);
    if (bb < bin) g_lbl[b*NANCH + sm_idx_of_n((int)(unsigned)e)] = -1;
    else if (bb == bin){
      int pos = atomicAdd(&s_s[4], 1);
      if (pos < TCAP) s_list[pos] = e;
    }
  }
  __syncthreads();
  int ec = s_s[4]; if (ec > TCAP) ec = TCAP;
  // rank each boundary-bin entry by (prio desc, n asc); disable rank >= rem
  for (int j = tid; j < ec; j += 256){
    unsigned long long ej = s_list[j];
    unsigned long long tj = (ej & 0xFFFFFFFF00000000ull) | (0xFFFFFFFFu - (unsigned)ej);
    int rank = 0;
    for (int i = 0; i < ec; i++){
      unsigned long long ei = s_list[i];
      unsigned long long ti = (ei & 0xFFFFFFFF00000000ull) | (0xFFFFFFFFu - (unsigned)ei);
      rank += (ti > tj);
    }
    if (rank >= rem) g_lbl[b*NANCH + sm_idx_of_n((int)(unsigned)ej)] = -1;
  }
  __syncthreads();
}

// ---------------- kernel 2: labels + targets + compaction + FUSED selection --
// Last-finishing block of each batch (fence + counter) runs both selections.
// Selection smem = 8KB hist + 4KB list: 8 blocks/SM x ~14KB < 228KB -> no
// occupancy loss (this is what broke the round-9 attempt at 33KB).
__global__ void k_label(const float* __restrict__ gt, float* __restrict__ out,
                        int B, int K){
  int b = blockIdx.y;
  __shared__ float sgx1[MAXK], sgy1[MAXK], sgx2[MAXK], sgy2[MAXK], sga[MAXK], sgm[MAXK];
  __shared__ uint2 s_kf, s_kb;
  __shared__ int   s_hist[2048];
  __shared__ int   s_w8[8];
  __shared__ unsigned long long s_tlist[TCAP];
  __shared__ int   s_s[8];
  __shared__ int   s_rank;
  int t = threadIdx.x;
  if (t < K){
    float g0 = gt[(b*K+t)*5+0], g1 = gt[(b*K+t)*5+1];
    float g2 = gt[(b*K+t)*5+2], g3 = gt[(b*K+t)*5+3];
    sgx1[t]=g0; sgy1[t]=g1; sgx2[t]=g2; sgy2[t]=g3;
    sga[t] = __fmul_rn(__fadd_rn(__fsub_rn(g2,g0),1.f),
                       __fadd_rn(__fsub_rn(g3,g1),1.f));
    sgm[t] = __int_as_float(g_gtmax[b*MAXK+t]);   // 0 => no inside anchor hits this gt
  }
  // jax.random.key(42) -> (0,42); foldlike split: key_b = block(root,0,b)
  if (t == 0){
    uint2 root = threefry(0u, 42u, 0u, (unsigned)b);
    s_kf = threefry(root.x, root.y, 0u, 0u);
  }
  if (t == 1){
    uint2 root = threefry(0u, 42u, 0u, (unsigned)b);
    s_kb = threefry(root.x, root.y, 0u, 1u);
  }
  __syncthreads();

  int idx2 = blockIdx.x*blockDim.x + t;
  int a = idx2 >> 12, loc = idx2 & (LOCS-1);
  int sidx = b*NANCH + idx2;
  float mo = g_maxovr[sidx];
  signed char L;
  float t0=0.f, t1=0.f, t2=0.f, t3=0.f;
  if (mo < 0.f){
    L = -2;
  } else {
    L = (mo < 0.3f) ? 0 : -1;
    bool best = false;
    int cnt = (int)g_ccnt[sidx];
    int x = loc & (HW-1), y = loc >> 6;
    float ax1 = c_base[a*4+0] + 16.f*(float)x;
    float ay1 = c_base[a*4+1] + 16.f*(float)y;
    float ax2 = c_base[a*4+2] + 16.f*(float)x;
    float ay2 = c_base[a*4+3] + 16.f*(float)y;
    if (cnt <= SLOTS){
      for (int i = 0; i < cnt; i++){
        unsigned long long e = g_cand[(size_t)sidx*SLOTS + i];
        int k = (int)(unsigned)e;
        float ovr = __uint_as_float((unsigned)(e >> 32));
        if (ovr == sgm[k]) best = true;
      }
    } else {
      // rare fallback: exact recompute with per-thread prune
      float aw = __fadd_rn(__fsub_rn(ax2,ax1),1.f);
      float ah = __fadd_rn(__fsub_rn(ay2,ay1),1.f);
      float aarea = __fmul_rn(aw, ah);
      for (int k = 0; k < K; k++){
        float gm = sgm[k];
        if (gm <= 0.f || gm > mo) continue;
        float ovr = iou_exact(ax1,ay1,ax2,ay2,aarea,
                              sgx1[k],sgy1[k],sgx2[k],sgy2[k],sga[k]);
        if (ovr == gm) best = true;
      }
    }
    if (best) L = 1;
    if (mo >= 0.7f) L = 1;
    // ---- targets (independent of subsampling; tolerance-safe fast math) ----
    {
      float aw = ax2-ax1+1.f, ah = ay2-ay1+1.f;
      float inv_aw = 1.f/aw, inv_ah = 1.f/ah;
      float acx = ax1 + 0.5f*(aw-1.f), acy = ay1 + 0.5f*(ah-1.f);
      int k = (int)g_arg[sidx];
      float g0 = sgx1[k], g1 = sgy1[k], g2 = sgx2[k], g3 = sgy2[k];
      float gw = g2-g0+1.f, gh = g3-g1+1.f;
      float gcx = g0 + 0.5f*(gw-1.f), gcy = g1 + 0.5f*(gh-1.f);
      t0 = (gcx-acx)*inv_aw;
      t1 = (gcy-acy)*inv_ah;
      t2 = __logf(gw*inv_aw);
      t3 = __logf(gh*inv_ah);
    }
  }
  g_lbl[sidx] = L;
  // targets planes: out[B*NANCH + ((b*36 + a*4 + j)*LOCS + loc)]
  {
    size_t p = (size_t)B*NANCH + ((size_t)b*36 + (size_t)a*4)*LOCS + loc;
    out[p           ] = t0;
    out[p +   LOCS  ] = t1;
    out[p + 2*LOCS  ] = t2;
    out[p + 3*LOCS  ] = t3;
  }

  // ---- fused candidate compaction (warp-aggregated global append) ----
  int n = loc*A_LOC + a;                        // ORIGINAL anchor index
  bool isfg = (L == 1), isbg = (L == 0);
  unsigned mfg = __ballot_sync(0xffffffffu, isfg);
  unsigned mbg = __ballot_sync(0xffffffffu, isbg);
  int lane = t & 31;
  if (isfg){
    unsigned prio = uniform_m23(s_kf.x, s_kf.y, (unsigned)n);
    int ldr = __ffs(mfg) - 1;
    int pos;
    if (lane == ldr) pos = atomicAdd(&g_cnt[b*2+0], __popc(mfg));
    pos = __shfl_sync(mfg, pos, ldr);
    pos += __popc(mfg & ((1u << lane) - 1u));
    g_fg[b*NANCH + pos] = ((unsigned long long)prio << 32) | (unsigned)n;
  }
  if (isbg){
    unsigned prio = uniform_m23(s_kb.x, s_kb.y, (unsigned)n);
    int ldr = __ffs(mbg) - 1;
    int pos;
    if (lane == ldr) pos = atomicAdd(&g_cnt[b*2+1], __popc(mbg));
    pos = __shfl_sync(mbg, pos, ldr);
    pos += __popc(mbg & ((1u << lane) - 1u));
    g_bg[b*NANCH + pos] = ((unsigned long long)prio << 32) | (unsigned)n;
  }

  // ---- fused subsampling: last block of this batch runs both selections ----
  __threadfence();                              // release our writes
  if (t == 0) s_rank = atomicAdd(&g_done[b], 1);
  __syncthreads();
  if (s_rank == (int)gridDim.x - 1){
    __threadfence();                            // acquire all blocks' writes
    int cf = g_cnt[b*2+0];
    int cb = g_cnt[b*2+1];
    int kept_fg = cf < 128 ? cf : 128;
    do_select_256(&g_fg[b*NANCH], b, cf, 128, s_hist, s_w8, s_tlist, s_s);
    int limit_bg = 256 - kept_fg;
    do_select_256(&g_bg[b*NANCH], b, cb, limit_bg, s_hist, s_w8, s_tlist, s_s);
    if (t == 0){
      int kept_bg = cb < limit_bg ? cb : limit_bg;
      g_uw[b] = __fdiv_rn(1.f, (float)(kept_fg + kept_bg));
      g_done[b] = 0;                            // reset for next graph replay
    }
  }
}

// ---------------- kernel 3: labels + weights output (4 locs/thread) ----------
// Also restores g_gtmax / g_cnt to zero for the next launch (graph replay).
__global__ void k_out(float* __restrict__ out, int B){
  int b = blockIdx.z, a = blockIdx.y;
  int tid = threadIdx.x;
  if (blockIdx.x == 0 && a == 0 && b == 0){
    for (int i = tid; i < MAXB*MAXK; i += 256) g_gtmax[i] = 0;
    if (tid < MAXB*2) g_cnt[tid] = 0;
  }

  int loc0 = blockIdx.x*1024 + tid*4;
  int sidx0 = b*NANCH + a*LOCS + loc0;
  uchar4 lb4 = *reinterpret_cast<const uchar4*>(&g_lbl[sidx0]);
  unsigned char lbs[4] = {lb4.x, lb4.y, lb4.z, lb4.w};
  float uw = g_uw[b];

  float lab[4], iw[4], ow[4];
#pragma unroll
  for (int j = 0; j < 4; j++){
    signed char L = (signed char)lbs[j];
    lab[j] = (L == -2) ? 0.f : (float)L;
    iw[j]  = (L == 1) ? 1.f : 0.f;
    ow[j]  = (L == 0 || L == 1) ? uw : 0.f;
  }
  size_t labOff = (size_t)b*NANCH + (size_t)a*LOCS + loc0;
  *reinterpret_cast<float4*>(out + labOff) = make_float4(lab[0],lab[1],lab[2],lab[3]);

  size_t base_t = (size_t)B*NANCH;
  size_t planes = (size_t)B*36*LOCS;
  size_t p      = ((size_t)b*36 + (size_t)a*4)*LOCS + loc0;
  float4 iwv = make_float4(iw[0],iw[1],iw[2],iw[3]);
  float4 owv = make_float4(ow[0],ow[1],ow[2],ow[3]);
#pragma unroll
  for (int j = 0; j < 4; j++){
    *reinterpret_cast<float4*>(out + base_t +   planes   + p + (size_t)j*LOCS) = iwv;
    *reinterpret_cast<float4*>(out + base_t + 2*planes   + p + (size_t)j*LOCS) = owv;
  }
}

// ---------------- launch -----------------------------------------------------
extern "C" void kernel_launch(void* const* d_in, const int* in_sizes, int n_in,
                              void* d_out, int out_size){
  const float* gt     = (const float*)d_in[1];
  const float* iminfo = (const float*)d_in[2];
  float* out = (float*)d_out;

  int B = in_sizes[0] / (2*A_LOC*LOCS);     // rpn_cls_score: B x 18 x 64 x 64
  int K = in_sizes[1] / (5*B);              // gt_boxes:      B x K x 5
  if (B > MAXB) B = MAXB;
  if (K > MAXK) K = MAXK;

  dim3 g1(NANCH/256, B);
  k_iou  <<<g1, 256>>>(gt, iminfo, K);
  k_label<<<g1, 256>>>(gt, out, B, K);
  k_out  <<<dim3(LOCS/1024, A_LOC, B), 256>>>(out, B);
}

// round 16
// speedup vs baseline: 1.2490x; 1.2490x over previous
#include <cuda_runtime.h>
#include <stdint.h>

// ---------------- problem constants (B=16, H=W=64, A=9, K=50) ----------------
#define A_LOC 9
#define HW    64
#define LOCS  (HW*HW)          // 4096
#define NANCH (LOCS*A_LOC)     // 36864
#define MAXB  16
#define MAXK  64
#define SLOTS 6
#define TIECAP 2048

// shape-major storage index for anchor (a, loc):  a*LOCS + loc
// original (reference) anchor index:              loc*A_LOC + a

// ---------------- device scratch (no allocations allowed) --------------------
__device__ float              g_maxovr[MAXB*NANCH];     // shape-major; -1 = outside
__device__ unsigned char      g_arg   [MAXB*NANCH];     // shape-major
__device__ signed char        g_lbl   [MAXB*NANCH];     // shape-major; -2 out,-1 dc,0 bg,1 fg
__device__ unsigned char      g_ccnt  [MAXB*NANCH];     // candidate count (sat 255)
__device__ unsigned long long g_cand  [(size_t)MAXB*NANCH*SLOTS]; // (ovr_bits<<32)|k
__device__ int                g_gtmax [MAXB*MAXK];      // float bits; zeroed by k_out
__device__ float              g_uw    [MAXB];
__device__ int                g_cnt   [MAXB*2];         // fg,bg counts; zeroed by k_out
__device__ unsigned long long g_fg    [MAXB*NANCH];     // (prio<<32)|orig_n
__device__ unsigned long long g_bg    [MAXB*NANCH];

// 9 base anchors (exact integers), order: ratio {0.5,1,2} x scale {8,16,32}
__constant__ float c_base[36] = {
  -84.f, -40.f,  99.f,  55.f,
 -176.f, -88.f, 191.f, 103.f,
 -360.f,-184.f, 375.f, 199.f,
  -56.f, -56.f,  71.f,  71.f,
 -120.f,-120.f, 135.f, 135.f,
 -248.f,-248.f, 263.f, 263.f,
  -36.f, -80.f,  51.f,  95.f,
  -80.f,-168.f,  95.f, 183.f,
 -168.f,-344.f, 183.f, 359.f
};

// ---------------- threefry2x32 (20 rounds), matches jax threefry2x32_p -------
__device__ __forceinline__ void tf_round(unsigned &x0, unsigned &x1, int r){
  x0 += x1; x1 = (x1 << r) | (x1 >> (32 - r)); x1 ^= x0;
}
__device__ __forceinline__ uint2 threefry(unsigned k0, unsigned k1,
                                          unsigned x0, unsigned x1){
  unsigned k2 = k0 ^ k1 ^ 0x1BD11BDAu;
  x0 += k0; x1 += k1;
  tf_round(x0,x1,13); tf_round(x0,x1,15); tf_round(x0,x1,26); tf_round(x0,x1,6);
  x0 += k1; x1 += k2 + 1u;
  tf_round(x0,x1,17); tf_round(x0,x1,29); tf_round(x0,x1,16); tf_round(x0,x1,24);
  x0 += k2; x1 += k0 + 2u;
  tf_round(x0,x1,13); tf_round(x0,x1,15); tf_round(x0,x1,26); tf_round(x0,x1,6);
  x0 += k0; x1 += k1 + 3u;
  tf_round(x0,x1,17); tf_round(x0,x1,29); tf_round(x0,x1,16); tf_round(x0,x1,24);
  x0 += k1; x1 += k2 + 4u;
  tf_round(x0,x1,13); tf_round(x0,x1,15); tf_round(x0,x1,26); tf_round(x0,x1,6);
  x0 += k2; x1 += k0 + 5u;
  return make_uint2(x0, x1);
}
__device__ __forceinline__ unsigned uniform_m23(unsigned k0, unsigned k1, unsigned idx){
  uint2 r = threefry(k0, k1, 0u, idx);
  return (r.x ^ r.y) >> 9;   // 23-bit mantissa bits; monotone in the uniform value
}

// exact IoU with reference rounding (strict rn ops, no fma contraction)
__device__ __forceinline__ float iou_exact(float ax1,float ay1,float ax2,float ay2,
                                           float aarea,
                                           float g0,float g1,float g2,float g3,float ga){
  float ix = fmaxf(0.f, __fadd_rn(__fsub_rn(fminf(ax2,g2), fmaxf(ax1,g0)),1.f));
  float iy = fmaxf(0.f, __fadd_rn(__fsub_rn(fminf(ay2,g3), fmaxf(ay1,g1)),1.f));
  float inter = __fmul_rn(ix, iy);
  float uni   = __fsub_rn(__fadd_rn(aarea, ga), inter);
  return __fdiv_rn(inter, uni);
}

// ---------------- kernel 1: IoU via intersection bitmasks (512 thr/block) ----
// Requires g_gtmax == 0 on entry (restored by k_out at end of previous launch).
// 8-row band per block halves block count -> halves prologue/mask/tail cost.
// Tail: only publish s_gm[k] if it beats the (deterministic) prime, except
// block x==0 which publishes the prime itself.
__global__ void k_iou(const float* __restrict__ gt, const float* __restrict__ iminfo, int K){
  int b = blockIdx.y;
  __shared__ float4 s_rej[MAXK];               // (g0-1.001, g2+1.001, g1-1.001, g3+1.001)
  __shared__ float4 s_box[MAXK];               // exact gt coords
  __shared__ float  s_area[MAXK];
  __shared__ int    s_gm[MAXK];
  __shared__ int    s_prime[MAXK];
  __shared__ unsigned long long s_xmask[64];
  __shared__ unsigned long long s_ymask[8];
  int t = threadIdx.x;
  int idx0 = blockIdx.x*512;                  // shape-major base for this block
  int a    = idx0 >> 12;
  int y0b  = (idx0 & (LOCS-1)) >> 6;          // first y row of the 8-row band
  float imh = iminfo[0], imw = iminfo[1];
  float bx1a = c_base[a*4+0], by1a = c_base[a*4+1];
  float bx2a = c_base[a*4+2], by2a = c_base[a*4+3];
  if (t < MAXK){ s_gm[t] = 0; s_prime[t] = 0; }
  if (t < K){
    float g0 = gt[(b*K+t)*5+0], g1 = gt[(b*K+t)*5+1];
    float g2 = gt[(b*K+t)*5+2], g3 = gt[(b*K+t)*5+3];
    s_box[t] = make_float4(g0, g1, g2, g3);
    s_rej[t] = make_float4(g0 - 1.001f, g2 + 1.001f, g1 - 1.001f, g3 + 1.001f);
    float ga = __fmul_rn(__fadd_rn(__fsub_rn(g2,g0),1.f),
                         __fadd_rn(__fsub_rn(g3,g1),1.f));
    s_area[t] = ga;
    // ---- prime with one heuristic probe anchor (sound, deterministic) ----
    float gw = g2-g0+1.f, gh = g3-g1+1.f;
    int r  = (gw > 1.42f*gh) ? 0 : ((gh > 1.42f*gw) ? 2 : 1);
    float m = fmaxf(gw, gh);
    int sc = (m < 181.f) ? 0 : ((m < 362.f) ? 1 : 2);
    int pa = r*3 + sc;
    float bx1 = c_base[pa*4+0], by1 = c_base[pa*4+1];
    float bx2 = c_base[pa*4+2], by2 = c_base[pa*4+3];
    int xlo = (int)ceilf(-bx1*0.0625f);          if (xlo < 0)  xlo = 0;
    int xhi = (int)ceilf((imw-bx2)*0.0625f) - 1; if (xhi > 63) xhi = 63;
    int ylo = (int)ceilf(-by1*0.0625f);          if (ylo < 0)  ylo = 0;
    int yhi = (int)ceilf((imh-by2)*0.0625f) - 1; if (yhi > 63) yhi = 63;
    if (xlo <= xhi && ylo <= yhi){
      float gcx = 0.5f*(g0+g2), gcy = 0.5f*(g1+g3);
      int px = __float2int_rn((gcx - 7.5f)*0.0625f);
      int py = __float2int_rn((gcy - 7.5f)*0.0625f);
      px = px < xlo ? xlo : (px > xhi ? xhi : px);
      py = py < ylo ? ylo : (py > yhi ? yhi : py);
      float ax1 = bx1 + 16.f*(float)px, ay1 = by1 + 16.f*(float)py;
      float ax2 = bx2 + 16.f*(float)px, ay2 = by2 + 16.f*(float)py;
      if (ax1 >= 0.f && ay1 >= 0.f && ax2 < imw && ay2 < imh){   // exact inside
        float aw = __fadd_rn(__fsub_rn(ax2,ax1),1.f);
        float ah = __fadd_rn(__fsub_rn(ay2,ay1),1.f);
        float aarea = __fmul_rn(aw, ah);
        float o = iou_exact(ax1,ay1,ax2,ay2,aarea, g0,g1,g2,g3,ga);
        if (o > 0.f){ s_gm[t] = (int)__float_as_int(o); s_prime[t] = s_gm[t]; }
      }
    }
  }
  __syncthreads();
  // ---- build column/row intersection bitmasks (conservative superset) ----
  if (t < 64){
    float ax1 = bx1a + 16.f*(float)t;
    float ax2 = bx2a + 16.f*(float)t;
    unsigned long long m = 0ull;
    for (int k = 0; k < K; k++){
      float4 rj = s_rej[k];
      if (ax2 > rj.x && ax1 < rj.y) m |= 1ull << k;
    }
    s_xmask[t] = m;
  } else if (t < 72){
    int row = t - 64;
    float ay1 = by1a + 16.f*(float)(y0b + row);
    float ay2 = by2a + 16.f*(float)(y0b + row);
    unsigned long long m = 0ull;
    for (int k = 0; k < K; k++){
      float4 rj = s_rej[k];
      if (ay2 > rj.z && ay1 < rj.w) m |= 1ull << k;
    }
    s_ymask[row] = m;
  }
  __syncthreads();

  int idx2 = idx0 + t;
  int loc = idx2 & (LOCS-1);
  int x = loc & (HW-1), y = loc >> 6;
  float ax1 = bx1a + 16.f*(float)x;
  float ay1 = by1a + 16.f*(float)y;
  float ax2 = bx2a + 16.f*(float)x;
  float ay2 = by2a + 16.f*(float)y;
  bool inside = (ax1 >= 0.f) && (ay1 >= 0.f) && (ax2 < imw) && (ay2 < imh);
  int sidx = b*NANCH + idx2;
  volatile int* vgm = s_gm;

  if (inside){
    float aw = __fadd_rn(__fsub_rn(ax2,ax1),1.f);
    float ah = __fadd_rn(__fsub_rn(ay2,ay1),1.f);
    float aarea = __fmul_rn(aw, ah);
    float mo = 0.f; int ma = 0, ccnt = 0;
    unsigned long long m = s_xmask[x] & s_ymask[y - y0b];
    while (m){
      int k = __ffsll((long long)m) - 1;        // ascending k => argmax = first max
      m &= m - 1ull;
      float4 gb = s_box[k];
      float ix = __fadd_rn(__fsub_rn(fminf(ax2,gb.z), fmaxf(ax1,gb.x)),1.f);
      float iy = __fadd_rn(__fsub_rn(fminf(ay2,gb.w), fmaxf(ay1,gb.y)),1.f);
      if (ix > 0.f && iy > 0.f){                // exact decision, unchanged
        float inter = __fmul_rn(ix, iy);
        float uni   = __fsub_rn(__fadd_rn(aarea, s_area[k]), inter);
        float ovr   = __fdiv_rn(inter, uni);
        if (ovr > mo){ mo = ovr; ma = k; }
        int bits = (int)__float_as_int(ovr);    // ovr > 0 => positive int order
        int cur = vgm[k];                       // broadcast LDS, conflict-free
        if (bits >= cur){                       // can still tie the final max
          atomicMax(&s_gm[k], bits);
          if (ccnt < SLOTS)
            g_cand[(size_t)sidx*SLOTS + ccnt] =
              ((unsigned long long)(unsigned)bits << 32) | (unsigned)k;
          ccnt++;
        }
      }
    }
    g_maxovr[sidx] = mo;
    g_arg   [sidx] = (unsigned char)ma;
    g_ccnt  [sidx] = (unsigned char)(ccnt > 255 ? 255 : ccnt);
  } else {
    g_maxovr[sidx] = -1.f;
  }
  __syncthreads();
  // tail: publish only if beating the prime (block 0 publishes the prime too)
  if (t < K){
    int sg = s_gm[t];
    if (sg && (sg > s_prime[t] || blockIdx.x == 0))
      atomicMax(&g_gtmax[b*MAXK+t], sg);
  }
}

// ---------------- kernel 2: labels + compaction + TARGETS planes -------------
__global__ void k_label(const float* __restrict__ gt, float* __restrict__ out,
                        int B, int K){
  int b = blockIdx.y;
  __shared__ float sgx1[MAXK], sgy1[MAXK], sgx2[MAXK], sgy2[MAXK], sga[MAXK], sgm[MAXK];
  __shared__ uint2 s_kf, s_kb;
  int t = threadIdx.x;
  if (t < K){
    float g0 = gt[(b*K+t)*5+0], g1 = gt[(b*K+t)*5+1];
    float g2 = gt[(b*K+t)*5+2], g3 = gt[(b*K+t)*5+3];
    sgx1[t]=g0; sgy1[t]=g1; sgx2[t]=g2; sgy2[t]=g3;
    sga[t] = __fmul_rn(__fadd_rn(__fsub_rn(g2,g0),1.f),
                       __fadd_rn(__fsub_rn(g3,g1),1.f));
    sgm[t] = __int_as_float(g_gtmax[b*MAXK+t]);   // 0 => no inside anchor hits this gt
  }
  // jax.random.key(42) -> (0,42); foldlike split: key_b = block(root,0,b)
  if (t == 0){
    uint2 root = threefry(0u, 42u, 0u, (unsigned)b);
    s_kf = threefry(root.x, root.y, 0u, 0u);
  }
  if (t == 1){
    uint2 root = threefry(0u, 42u, 0u, (unsigned)b);
    s_kb = threefry(root.x, root.y, 0u, 1u);
  }
  __syncthreads();

  int idx2 = blockIdx.x*blockDim.x + t;
  int a = idx2 >> 12, loc = idx2 & (LOCS-1);
  int sidx = b*NANCH + idx2;
  float mo = g_maxovr[sidx];
  signed char L;
  float t0=0.f, t1=0.f, t2=0.f, t3=0.f;
  if (mo < 0.f){
    L = -2;
  } else {
    L = (mo < 0.3f) ? 0 : -1;
    bool best = false;
    int cnt = (int)g_ccnt[sidx];
    int x = loc & (HW-1), y = loc >> 6;
    float ax1 = c_base[a*4+0] + 16.f*(float)x;
    float ay1 = c_base[a*4+1] + 16.f*(float)y;
    float ax2 = c_base[a*4+2] + 16.f*(float)x;
    float ay2 = c_base[a*4+3] + 16.f*(float)y;
    if (cnt <= SLOTS){
      for (int i = 0; i < cnt; i++){
        unsigned long long e = g_cand[(size_t)sidx*SLOTS + i];
        int k = (int)(unsigned)e;
        float ovr = __uint_as_float((unsigned)(e >> 32));
        if (ovr == sgm[k]) best = true;
      }
    } else {
      // rare fallback: exact recompute with per-thread prune
      float aw = __fadd_rn(__fsub_rn(ax2,ax1),1.f);
      float ah = __fadd_rn(__fsub_rn(ay2,ay1),1.f);
      float aarea = __fmul_rn(aw, ah);
      for (int k = 0; k < K; k++){
        float gm = sgm[k];
        if (gm <= 0.f || gm > mo) continue;
        float ovr = iou_exact(ax1,ay1,ax2,ay2,aarea,
                              sgx1[k],sgy1[k],sgx2[k],sgy2[k],sga[k]);
        if (ovr == gm) best = true;
      }
    }
    if (best) L = 1;
    if (mo >= 0.7f) L = 1;
    // ---- targets (independent of subsampling; tolerance-safe fast math) ----
    {
      float aw = ax2-ax1+1.f, ah = ay2-ay1+1.f;
      float inv_aw = 1.f/aw, inv_ah = 1.f/ah;
      float acx = ax1 + 0.5f*(aw-1.f), acy = ay1 + 0.5f*(ah-1.f);
      int k = (int)g_arg[sidx];
      float g0 = sgx1[k], g1 = sgy1[k], g2 = sgx2[k], g3 = sgy2[k];
      float gw = g2-g0+1.f, gh = g3-g1+1.f;
      float gcx = g0 + 0.5f*(gw-1.f), gcy = g1 + 0.5f*(gh-1.f);
      t0 = (gcx-acx)*inv_aw;
      t1 = (gcy-acy)*inv_ah;
      t2 = __logf(gw*inv_aw);
      t3 = __logf(gh*inv_ah);
    }
  }
  g_lbl[sidx] = L;
  // targets planes: out[B*NANCH + ((b*36 + a*4 + j)*LOCS + loc)]
  {
    size_t p = (size_t)B*NANCH + ((size_t)b*36 + (size_t)a*4)*LOCS + loc;
    out[p           ] = t0;
    out[p +   LOCS  ] = t1;
    out[p + 2*LOCS  ] = t2;
    out[p + 3*LOCS  ] = t3;
  }

  // ---- fused candidate compaction (warp-aggregated global append) ----
  int n = loc*A_LOC + a;                        // ORIGINAL anchor index
  bool isfg = (L == 1), isbg = (L == 0);
  unsigned mfg = __ballot_sync(0xffffffffu, isfg);
  unsigned mbg = __ballot_sync(0xffffffffu, isbg);
  int lane = t & 31;
  if (isfg){
    unsigned prio = uniform_m23(s_kf.x, s_kf.y, (unsigned)n);
    int ldr = __ffs(mfg) - 1;
    int pos;
    if (lane == ldr) pos = atomicAdd(&g_cnt[b*2+0], __popc(mfg));
    pos = __shfl_sync(mfg, pos, ldr);
    pos += __popc(mfg & ((1u << lane) - 1u));
    g_fg[b*NANCH + pos] = ((unsigned long long)prio << 32) | (unsigned)n;
  }
  if (isbg){
    unsigned prio = uniform_m23(s_kb.x, s_kb.y, (unsigned)n);
    int ldr = __ffs(mbg) - 1;
    int pos;
    if (lane == ldr) pos = atomicAdd(&g_cnt[b*2+1], __popc(mbg));
    pos = __shfl_sync(mbg, pos, ldr);
    pos += __popc(mbg & ((1u << lane) - 1u));
    g_bg[b*NANCH + pos] = ((unsigned long long)prio << 32) | (unsigned)n;
  }
}

// ---------------- kernel 3: subsampling (fg and bg run in parallel blocks) ---
__device__ __forceinline__ int suffix_scan1024(int v, int* s_w){
  int tid = threadIdx.x, lane = tid & 31, wrp = tid >> 5;
  int s = v;
#pragma unroll
  for (int off = 1; off < 32; off <<= 1){
    int o = __shfl_down_sync(0xffffffffu, s, off);
    if (lane + off < 32) s += o;
  }
  if (lane == 0) s_w[wrp] = s;
  __syncthreads();
  if (wrp == 0){
    int tot = s_w[lane], s2 = tot;
#pragma unroll
    for (int off = 1; off < 32; off <<= 1){
      int o = __shfl_down_sync(0xffffffffu, s2, off);
      if (lane + off < 32) s2 += o;
    }
    s_w[lane] = s2 - tot;                       // sum of LATER warps
  }
  __syncthreads();
  return s + s_w[wrp];                          // suffix incl own value
}

__device__ __forceinline__ int sm_idx_of_n(int n){  // original n -> shape-major idx
  int a = n % A_LOC, loc = n / A_LOC;
  return a*LOCS + loc;
}

// Keep top-`limit` by (prio desc, index asc); mark the rest -1 in g_lbl.
// Level-1 histogram on prio[22:12] (2048 bins); exact tie-rank inside boundary bin.
__device__ void do_select_list(const unsigned long long* __restrict__ list,
                               int b, int cnt, int limit,
                               int* hist, int* s_w, unsigned long long* s_list, int* s_s){
  const int tid = threadIdx.x;
  if (cnt <= limit) return;

  for (int i = tid; i < 2048; i += 1024) hist[i] = 0;
  __syncthreads();
  for (int i = tid; i < cnt; i += 1024)
    atomicAdd(&hist[(unsigned)(list[i] >> 32) >> 12], 1);
  __syncthreads();
  int v = hist[2*tid] + hist[2*tid+1];
  int S = suffix_scan1024(v, s_w);
  if (S >= limit && S - v < limit){ s_s[0] = tid; s_s[1] = S - v; }
  __syncthreads();
  if (tid == 0){
    int g = s_s[0], acc = s_s[1];
    for (int q = 2*g+1; q >= 2*g; q--){
      acc += hist[q];
      if (acc >= limit){ s_s[2] = q; s_s[3] = limit - (acc - hist[q]); break; }
    }
    s_s[4] = 0;
  }
  __syncthreads();
  int bin = s_s[2], rem = s_s[3];

  // single disable/collect pass: bins below -> disable; boundary bin -> collect
  for (int i = tid; i < cnt; i += 1024){
    unsigned long long e = list[i];
    int bb = (int)((unsigned)(e >> 32) >> 12);
    if (bb < bin) g_lbl[b*NANCH + sm_idx_of_n((int)(unsigned)e)] = -1;
    else if (bb == bin){
      int pos = atomicAdd(&s_s[4], 1);
      if (pos < TIECAP) s_list[pos] = e;
    }
  }
  __syncthreads();
  int ec = s_s[4]; if (ec > TIECAP) ec = TIECAP;
  // rank each boundary-bin entry by (prio desc, n asc); disable rank >= rem
  for (int j = tid; j < ec; j += 1024){
    unsigned long long ej = s_list[j];
    unsigned long long tj = (ej & 0xFFFFFFFF00000000ull) | (0xFFFFFFFFu - (unsigned)ej);
    int rank = 0;
    for (int i = 0; i < ec; i++){
      unsigned long long ei = s_list[i];
      unsigned long long ti = (ei & 0xFFFFFFFF00000000ull) | (0xFFFFFFFFu - (unsigned)ei);
      rank += (ti > tj);
    }
    if (rank >= rem) g_lbl[b*NANCH + sm_idx_of_n((int)(unsigned)ej)] = -1;
  }
}

__global__ void k_sub(){
  int half = blockIdx.x, b = blockIdx.y;
  __shared__ int hist[2048];
  __shared__ int s_w[32];
  __shared__ unsigned long long s_list[TIECAP];
  __shared__ int s_s[8];
  int cf = g_cnt[b*2+0];
  int cb = g_cnt[b*2+1];
  int kept_fg = cf < 128 ? cf : 128;
  if (half == 0){
    do_select_list(&g_fg[b*NANCH], b, cf, 128, hist, s_w, s_list, s_s);
  } else {
    int limit_bg = 256 - kept_fg;
    do_select_list(&g_bg[b*NANCH], b, cb, limit_bg, hist, s_w, s_list, s_s);
    if (threadIdx.x == 0){
      int kept_bg = cb < limit_bg ? cb : limit_bg;
      g_uw[b] = __fdiv_rn(1.f, (float)(kept_fg + kept_bg));
    }
  }
}

// ---------------- kernel 4: labels + weights output (4 locs/thread) ----------
// Also restores g_gtmax / g_cnt to zero for the next launch (graph replay).
__global__ void k_out(float* __restrict__ out, int B){
  int b = blockIdx.z, a = blockIdx.y;
  int tid = threadIdx.x;
  if (blockIdx.x == 0 && a == 0 && b == 0){
    for (int i = tid; i < MAXB*MAXK; i += 256) g_gtmax[i] = 0;
    if (tid < MAXB*2) g_cnt[tid] = 0;
  }

  int loc0 = blockIdx.x*1024 + tid*4;
  int sidx0 = b*NANCH + a*LOCS + loc0;
  uchar4 lb4 = *reinterpret_cast<const uchar4*>(&g_lbl[sidx0]);
  unsigned char lbs[4] = {lb4.x, lb4.y, lb4.z, lb4.w};
  float uw = g_uw[b];

  float lab[4], iw[4], ow[4];
#pragma unroll
  for (int j = 0; j < 4; j++){
    signed char L = (signed char)lbs[j];
    lab[j] = (L == -2) ? 0.f : (float)L;
    iw[j]  = (L == 1) ? 1.f : 0.f;
    ow[j]  = (L == 0 || L == 1) ? uw : 0.f;
  }
  size_t labOff = (size_t)b*NANCH + (size_t)a*LOCS + loc0;
  *reinterpret_cast<float4*>(out + labOff) = make_float4(lab[0],lab[1],lab[2],lab[3]);

  size_t base_t = (size_t)B*NANCH;
  size_t planes = (size_t)B*36*LOCS;
  size_t p      = ((size_t)b*36 + (size_t)a*4)*LOCS + loc0;
  float4 iwv = make_float4(iw[0],iw[1],iw[2],iw[3]);
  float4 owv = make_float4(ow[0],ow[1],ow[2],ow[3]);
#pragma unroll
  for (int j = 0; j < 4; j++){
    *reinterpret_cast<float4*>(out + base_t +   planes   + p + (size_t)j*LOCS) = iwv;
    *reinterpret_cast<float4*>(out + base_t + 2*planes   + p + (size_t)j*LOCS) = owv;
  }
}

// ---------------- launch -----------------------------------------------------
extern "C" void kernel_launch(void* const* d_in, const int* in_sizes, int n_in,
                              void* d_out, int out_size){
  const float* gt     = (const float*)d_in[1];
  const float* iminfo = (const float*)d_in[2];
  float* out = (float*)d_out;

  int B = in_sizes[0] / (2*A_LOC*LOCS);     // rpn_cls_score: B x 18 x 64 x 64
  int K = in_sizes[1] / (5*B);              // gt_boxes:      B x K x 5
  if (B > MAXB) B = MAXB;
  if (K > MAXK) K = MAXK;

  k_iou  <<<dim3(NANCH/512, B), 512>>>(gt, iminfo, K);
  k_label<<<dim3(NANCH/256, B), 256>>>(gt, out, B, K);
  k_sub  <<<dim3(2, B), 1024>>>();
  k_out  <<<dim3(LOCS/1024, A_LOC, B), 256>>>(out, B);
}